// round 5
// baseline (speedup 1.0000x reference)
#include <cuda_runtime.h>
#include <math.h>
#include <stdint.h>

#define DIMF 128
#define N_LEGO 50000
#define N_POINT 100000
#define NE_LL 500000
#define NE_PP 400000
#define NE_LP 500000
#define NE_PL 500000
#define NEG_INF_KEY 0x007FFFFFu

// ---------------- scratch (static device allocations; no cudaMalloc) ----------------
__device__ float    g_xl[N_LEGO * DIMF];
__device__ float    g_xp[N_POINT * DIMF];
__device__ float    g_la[N_LEGO * DIMF];
__device__ float    g_pa[N_POINT * DIMF];
__device__ float    g_q[N_LEGO * DIMF];
__device__ float    g_k[N_LEGO * DIMF];
__device__ float    g_v[N_LEGO * DIMF];
__device__ float    g_hs[N_POINT * DIMF];
__device__ float    g_hd[N_POINT * DIMF];
__device__ float    g_ss[N_POINT];
__device__ float    g_sd[N_POINT];
__device__ float    g_escore[NE_LL];
__device__ unsigned g_mkey[N_POINT];
__device__ float    g_dsum[N_POINT];
__device__ float    g_P[N_POINT * 512];
__device__ float    g_Q[N_POINT * 512];
__device__ unsigned g_emax[N_POINT * DIMF];
__device__ float    g_Ahi[N_POINT * DIMF];
__device__ float    g_Alo[N_POINT * DIMF];
__device__ float    g_Bhi[65536];
__device__ float    g_Blo[65536];

// ---------------- helpers ----------------
__device__ __forceinline__ unsigned fkey(float f) {
    unsigned u = __float_as_uint(f);
    return (u & 0x80000000u) ? ~u : (u | 0x80000000u);
}
__device__ __forceinline__ float fdecode(unsigned kk) {
    unsigned u = (kk & 0x80000000u) ? (kk ^ 0x80000000u) : ~kk;
    return __uint_as_float(u);
}
__device__ __forceinline__ float to_tf32(float x) {
    float r;
    asm("cvt.rna.tf32.f32 %0, %1;" : "=f"(r) : "f"(x));
    return r;
}
__device__ __forceinline__ void cp_async16(void* dst, const void* src, int bytes) {
    uint32_t d = (uint32_t)__cvta_generic_to_shared(dst);
    asm volatile("cp.async.ca.shared.global [%0], [%1], 16, %2;\n"
                 :: "r"(d), "l"(src), "r"(bytes));
}

// ---------------- GEMM tiling ----------------
#define BM 128
#define BN 128
#define BK2 16
#define ASTR 20      // As[m][k]: banks 20g+t -> {0,20,8,28,16,4,24,12}+t, conflict-free
#define BSTR 136     // Bs[k][n]: banks 8t+g, conflict-free
// per-stage float offsets
#define AH_OFF 0
#define AL_OFF (BM * ASTR)                 // 2560
#define BH_OFF (2 * BM * ASTR)             // 5120
#define BL_OFF (2 * BM * ASTR + BK2 * BSTR)  // 7296
#define STAGE_F (2 * BM * ASTR + 2 * BK2 * BSTR)   // 9472
#define PS_SMEM_F (2 * STAGE_F)                    // 18944 floats = 75776 B
#define PS_SMEM_BYTES (PS_SMEM_F * sizeof(float))
#define EDGE_SMEM_BYTES (PS_SMEM_BYTES + 2 * BM * sizeof(int))

#define MMA_TF32(accv, a0, a1, a2, a3, b0, b1)                                     \
    asm("mma.sync.aligned.m16n8k8.row.col.f32.tf32.tf32.f32 "                      \
        "{%0,%1,%2,%3}, {%4,%5,%6,%7}, {%8,%9}, {%0,%1,%2,%3};"                    \
        : "+f"(accv[0]), "+f"(accv[1]), "+f"(accv[2]), "+f"(accv[3])               \
        : "r"(a0), "r"(a1), "r"(a2), "r"(a3), "r"(b0), "r"(b1))

// pure LDS+MMA compute over one pre-split stage (2 k-steps of 8)
#define PS_COMPUTE(st)                                                             \
    {                                                                              \
        const float* sb = smem + (st) * STAGE_F;                                   \
        _Pragma("unroll")                                                          \
        for (int ks = 0; ks < 2; ks++) {                                           \
            const int k0 = ks * 8;                                                 \
            uint32_t afh[2][4], afl[2][4];                                         \
            _Pragma("unroll")                                                      \
            for (int mt = 0; mt < 2; mt++) {                                       \
                int r0 = wm + mt * 16 + g;                                         \
                afh[mt][0] = __float_as_uint(sb[AH_OFF + r0 * ASTR + k0 + t]);     \
                afh[mt][1] = __float_as_uint(sb[AH_OFF + (r0 + 8) * ASTR + k0 + t]); \
                afh[mt][2] = __float_as_uint(sb[AH_OFF + r0 * ASTR + k0 + t + 4]); \
                afh[mt][3] = __float_as_uint(sb[AH_OFF + (r0 + 8) * ASTR + k0 + t + 4]); \
                afl[mt][0] = __float_as_uint(sb[AL_OFF + r0 * ASTR + k0 + t]);     \
                afl[mt][1] = __float_as_uint(sb[AL_OFF + (r0 + 8) * ASTR + k0 + t]); \
                afl[mt][2] = __float_as_uint(sb[AL_OFF + r0 * ASTR + k0 + t + 4]); \
                afl[mt][3] = __float_as_uint(sb[AL_OFF + (r0 + 8) * ASTR + k0 + t + 4]); \
            }                                                                      \
            _Pragma("unroll")                                                      \
            for (int nt = 0; nt < 8; nt++) {                                       \
                int nn = wn + nt * 8 + g;                                          \
                uint32_t bh0 = __float_as_uint(sb[BH_OFF + (k0 + t) * BSTR + nn]); \
                uint32_t bh1 = __float_as_uint(sb[BH_OFF + (k0 + t + 4) * BSTR + nn]); \
                uint32_t bl0 = __float_as_uint(sb[BL_OFF + (k0 + t) * BSTR + nn]); \
                uint32_t bl1 = __float_as_uint(sb[BL_OFF + (k0 + t + 4) * BSTR + nn]); \
                _Pragma("unroll")                                                  \
                for (int mt = 0; mt < 2; mt++) {                                   \
                    MMA_TF32(acc[mt][nt], afl[mt][0], afl[mt][1], afl[mt][2],      \
                             afl[mt][3], bh0, bh1);                                \
                    MMA_TF32(acc[mt][nt], afh[mt][0], afh[mt][1], afh[mt][2],      \
                             afh[mt][3], bl0, bl1);                                \
                    MMA_TF32(acc[mt][nt], afh[mt][0], afh[mt][1], afh[mt][2],      \
                             afh[mt][3], bh0, bh1);                                \
                }                                                                  \
            }                                                                      \
        }                                                                          \
    }

// ---------------- elementwise hi/lo split ----------------
__global__ void split_kernel(const float4* __restrict__ x, float4* __restrict__ hi,
                             float4* __restrict__ lo, int n4)
{
    int i = blockIdx.x * blockDim.x + threadIdx.x;
    if (i >= n4) return;
    float4 v = x[i];
    float4 h, l;
    h.x = to_tf32(v.x); l.x = to_tf32(v.x - h.x);
    h.y = to_tf32(v.y); l.y = to_tf32(v.y - h.y);
    h.z = to_tf32(v.z); l.z = to_tf32(v.z - h.z);
    h.w = to_tf32(v.w); l.w = to_tf32(v.w - h.w);
    hi[i] = h; lo[i] = l;
}

// ---------------- pre-split 3xTF32 GEMM: C[M,N] = A@B (+bias) ----------------
__global__ __launch_bounds__(256, 2) void mma3_ps_kernel(
    const float* __restrict__ Ahi, const float* __restrict__ Alo,
    const float* __restrict__ Bhi, const float* __restrict__ Blo,
    const float* __restrict__ bias, float* __restrict__ C,
    int M, int N, int K)
{
    extern __shared__ float smem[];
    const int tid  = threadIdx.x;
    const int warp = tid >> 5, lane = tid & 31;
    const int g = lane >> 2, t = lane & 3;
    const int warp_m = warp & 3, warp_n = warp >> 2;
    const int m_base = blockIdx.y * BM;
    const int n_base = blockIdx.x * BN;
    const int wm = warp_m * 32;
    const int wn = warp_n * 64;

    float acc[2][8][4];
#pragma unroll
    for (int i = 0; i < 2; i++)
#pragma unroll
        for (int j = 0; j < 8; j++)
#pragma unroll
            for (int c = 0; c < 4; c++) acc[i][j][c] = 0.f;

#define PS_ISSUE(k0, st)                                                           \
    {                                                                              \
        float* sb = smem + (st) * STAGE_F;                                         \
        _Pragma("unroll")                                                          \
        for (int i = 0; i < 2; i++) {                                              \
            int idx = tid + i * 256;                                               \
            int row = idx >> 2, c4 = (idx & 3) * 4;                                \
            int gr = m_base + row;                                                 \
            int ok = (gr < M) ? 16 : 0;                                            \
            size_t aoff = (size_t)gr * K + (k0) + c4;                              \
            cp_async16(sb + AH_OFF + row * ASTR + c4, Ahi + aoff, ok);             \
            cp_async16(sb + AL_OFF + row * ASTR + c4, Alo + aoff, ok);             \
        }                                                                          \
        _Pragma("unroll")                                                          \
        for (int i = 0; i < 2; i++) {                                              \
            int idx = tid + i * 256;                                               \
            int row = idx >> 5, c4 = (idx & 31) * 4;                               \
            size_t boff = (size_t)((k0) + row) * N + n_base + c4;                  \
            cp_async16(sb + BH_OFF + row * BSTR + c4, Bhi + boff, 16);             \
            cp_async16(sb + BL_OFF + row * BSTR + c4, Blo + boff, 16);             \
        }                                                                          \
        asm volatile("cp.async.commit_group;\n" ::);                               \
    }

    PS_ISSUE(0, 0);

    int stage = 0;
    for (int kt = 0; kt < K; kt += BK2, stage ^= 1) {
        const bool more = (kt + BK2) < K;
        if (more) PS_ISSUE(kt + BK2, stage ^ 1);
        if (more) asm volatile("cp.async.wait_group 1;\n" ::);
        else      asm volatile("cp.async.wait_group 0;\n" ::);
        __syncthreads();
        PS_COMPUTE(stage);
        __syncthreads();
    }

#pragma unroll
    for (int mt = 0; mt < 2; mt++) {
        int r0 = m_base + wm + mt * 16 + g;
        int r1 = r0 + 8;
#pragma unroll
        for (int nt = 0; nt < 8; nt++) {
            int c = n_base + wn + nt * 8 + 2 * t;
            float b0 = 0.f, b1 = 0.f;
            if (bias) { b0 = bias[c]; b1 = bias[c + 1]; }
            if (r0 < M) {
                float2 v0 = make_float2(acc[mt][nt][0] + b0, acc[mt][nt][1] + b1);
                *(float2*)(C + (size_t)r0 * N + c) = v0;
            }
            if (r1 < M) {
                float2 v1 = make_float2(acc[mt][nt][2] + b0, acc[mt][nt][3] + b1);
                *(float2*)(C + (size_t)r1 * N + c) = v1;
            }
        }
    }
}

// ---------------- fused EdgeConv MLP2 + segment-max GEMM (pre-split W2) ----------------
// A[e,k] = relu(P[dst,k] - Q[dst,k] + Q[src,k] + b1[k]), split at gather time.
__global__ __launch_bounds__(256, 2) void edge_fused_ps_kernel(
    const float* __restrict__ P, const float* __restrict__ Q,
    const float* __restrict__ b1,
    const float* __restrict__ W2hi, const float* __restrict__ W2lo,
    const int* __restrict__ src, const int* __restrict__ dst,
    unsigned* __restrict__ emax, int E)
{
    extern __shared__ float smem[];
    int* se = (int*)(smem + PS_SMEM_F);
    int* de = se + BM;

    const int tid  = threadIdx.x;
    const int warp = tid >> 5, lane = tid & 31;
    const int g = lane >> 2, t = lane & 3;
    const int warp_m = warp & 3, warp_n = warp >> 2;
    const int e_base = blockIdx.y * BM;
    const int wm = warp_m * 32;
    const int wn = warp_n * 64;
    const int KTOT = 512;

    if (tid < BM) {
        int e = e_base + tid;
        bool ok = (e < E);
        se[tid] = ok ? src[e] : 0;
        de[tid] = ok ? dst[e] : 0;
    }
    __syncthreads();

    float acc[2][8][4];
#pragma unroll
    for (int i = 0; i < 2; i++)
#pragma unroll
        for (int j = 0; j < 8; j++)
#pragma unroll
            for (int c = 0; c < 4; c++) acc[i][j][c] = 0.f;

#define EF_ISSUE_B(k0, st)                                                         \
    {                                                                              \
        float* sb = smem + (st) * STAGE_F;                                         \
        _Pragma("unroll")                                                          \
        for (int i = 0; i < 2; i++) {                                              \
            int idx = tid + i * 256;                                               \
            int row = idx >> 5, c4 = (idx & 31) * 4;                               \
            size_t boff = (size_t)((k0) + row) * 128 + c4;                         \
            cp_async16(sb + BH_OFF + row * BSTR + c4, W2hi + boff, 16);            \
            cp_async16(sb + BL_OFF + row * BSTR + c4, W2lo + boff, 16);            \
        }                                                                          \
        asm volatile("cp.async.commit_group;\n" ::);                               \
    }

#define EF_GATHER(k0, st)                                                          \
    {                                                                              \
        float* sb = smem + (st) * STAGE_F;                                         \
        _Pragma("unroll")                                                          \
        for (int i = 0; i < 2; i++) {                                              \
            int idx = tid + i * 256;                                               \
            int row = idx >> 2, c4 = (idx & 3) * 4;                                \
            int s0 = se[row], d0 = de[row];                                        \
            float4 pv = *(const float4*)(P + (size_t)d0 * 512 + (k0) + c4);        \
            float4 qd = *(const float4*)(Q + (size_t)d0 * 512 + (k0) + c4);        \
            float4 qs = *(const float4*)(Q + (size_t)s0 * 512 + (k0) + c4);        \
            float4 bb = *(const float4*)(b1 + (k0) + c4);                          \
            float4 h, hv, lv;                                                      \
            h.x = fmaxf(pv.x - qd.x + qs.x + bb.x, 0.f);                           \
            h.y = fmaxf(pv.y - qd.y + qs.y + bb.y, 0.f);                           \
            h.z = fmaxf(pv.z - qd.z + qs.z + bb.z, 0.f);                           \
            h.w = fmaxf(pv.w - qd.w + qs.w + bb.w, 0.f);                           \
            hv.x = to_tf32(h.x); lv.x = to_tf32(h.x - hv.x);                       \
            hv.y = to_tf32(h.y); lv.y = to_tf32(h.y - hv.y);                       \
            hv.z = to_tf32(h.z); lv.z = to_tf32(h.z - hv.z);                       \
            hv.w = to_tf32(h.w); lv.w = to_tf32(h.w - hv.w);                       \
            *(float4*)(sb + AH_OFF + row * ASTR + c4) = hv;                        \
            *(float4*)(sb + AL_OFF + row * ASTR + c4) = lv;                        \
        }                                                                          \
    }

    EF_GATHER(0, 0);
    EF_ISSUE_B(0, 0);

    int stage = 0;
    for (int kt = 0; kt < KTOT; kt += BK2, stage ^= 1) {
        const bool more = (kt + BK2) < KTOT;
        if (more) EF_ISSUE_B(kt + BK2, stage ^ 1);
        if (more) asm volatile("cp.async.wait_group 1;\n" ::);
        else      asm volatile("cp.async.wait_group 0;\n" ::);
        __syncthreads();
        PS_COMPUTE(stage);
        if (more) EF_GATHER(kt + BK2, stage ^ 1);
        __syncthreads();
    }

    // epilogue: segment-max via monotone-uint atomicMax
#pragma unroll
    for (int mt = 0; mt < 2; mt++) {
        int r0 = wm + mt * 16 + g;
        int r1 = r0 + 8;
        int e0 = e_base + r0, e1 = e_base + r1;
        int d0 = de[r0], d1 = de[r1];
#pragma unroll
        for (int nt = 0; nt < 8; nt++) {
            int c = wn + nt * 8 + 2 * t;
            if (e0 < E) {
                atomicMax(emax + (size_t)d0 * DIMF + c,     fkey(acc[mt][nt][0]));
                atomicMax(emax + (size_t)d0 * DIMF + c + 1, fkey(acc[mt][nt][1]));
            }
            if (e1 < E) {
                atomicMax(emax + (size_t)d1 * DIMF + c,     fkey(acc[mt][nt][2]));
                atomicMax(emax + (size_t)d1 * DIMF + c + 1, fkey(acc[mt][nt][3]));
            }
        }
    }
}

// ---------------- graph kernels ----------------
__global__ void reset_softmax_kernel(unsigned* mkey, float* dsum, int n) {
    int i = blockIdx.x * blockDim.x + threadIdx.x;
    if (i < n) { mkey[i] = NEG_INF_KEY; dsum[i] = 0.f; }
}

__global__ void fill_u32_kernel(unsigned* p, unsigned val, int n) {
    int i = blockIdx.x * blockDim.x + threadIdx.x;
    if (i < n) p[i] = val;
}

__global__ void trans_score_kernel(
    const float* __restrict__ q, const float* __restrict__ k,
    const int* __restrict__ src, const int* __restrict__ dst,
    float* __restrict__ score, unsigned* __restrict__ mkey, int E, float scale)
{
    int idx = blockIdx.x * blockDim.x + threadIdx.x;
    int e = idx >> 5, lane = idx & 31;
    if (e >= E) return;
    int d = dst[e], s0 = src[e];
    float4 qv = *(const float4*)(q + (size_t)d * DIMF + lane * 4);
    float4 kv = *(const float4*)(k + (size_t)s0 * DIMF + lane * 4);
    float s = qv.x * kv.x + qv.y * kv.y + qv.z * kv.z + qv.w * kv.w;
#pragma unroll
    for (int o = 16; o; o >>= 1) s += __shfl_xor_sync(0xffffffffu, s, o);
    if (lane == 0) {
        s *= scale;
        score[e] = s;
        atomicMax(mkey + d, fkey(s));
    }
}

__global__ void node_dot_kernel(const float* __restrict__ h, const float* __restrict__ avec,
                                float* __restrict__ out, int n)
{
    int idx = blockIdx.x * blockDim.x + threadIdx.x;
    int i = idx >> 5, lane = idx & 31;
    if (i >= n) return;
    float4 hv = *(const float4*)(h + (size_t)i * DIMF + lane * 4);
    float4 av = *(const float4*)(avec + lane * 4);
    float s = hv.x * av.x + hv.y * av.y + hv.z * av.z + hv.w * av.w;
#pragma unroll
    for (int o = 16; o; o >>= 1) s += __shfl_xor_sync(0xffffffffu, s, o);
    if (lane == 0) out[i] = s;
}

__global__ void gat_score_kernel(const float* __restrict__ ss, const float* __restrict__ sd,
                                 const int* __restrict__ src, const int* __restrict__ dst,
                                 float* __restrict__ score, unsigned* __restrict__ mkey, int E)
{
    int e = blockIdx.x * blockDim.x + threadIdx.x;
    if (e >= E) return;
    float s = ss[src[e]] + sd[dst[e]];
    s = (s > 0.f) ? s : 0.2f * s;
    score[e] = s;
    atomicMax(mkey + dst[e], fkey(s));
}

__global__ void expsum_kernel(float* __restrict__ score, const unsigned* __restrict__ mkey,
                              float* __restrict__ dsum, const int* __restrict__ dst, int E)
{
    int e = blockIdx.x * blockDim.x + threadIdx.x;
    if (e >= E) return;
    int d = dst[e];
    float m = fdecode(mkey[d]);
    if (!isfinite(m)) m = 0.f;
    float ex = expf(score[e] - m);
    score[e] = ex;
    atomicAdd(dsum + d, ex);
}

__global__ void aggregate_kernel(const float* __restrict__ score, const float* __restrict__ dsum,
                                 const float* __restrict__ v,
                                 const int* __restrict__ src, const int* __restrict__ dst,
                                 float* __restrict__ out, int E)
{
    int idx = blockIdx.x * blockDim.x + threadIdx.x;
    int e = idx >> 5, lane = idx & 31;
    if (e >= E) return;
    int d = dst[e], s0 = src[e];
    float w = score[e] / (dsum[d] + 1e-16f);
    float4 vv = *(const float4*)(v + (size_t)s0 * DIMF + lane * 4);
    float* op = out + (size_t)d * DIMF + lane * 4;
    atomicAdd(op + 0, w * vv.x);
    atomicAdd(op + 1, w * vv.y);
    atomicAdd(op + 2, w * vv.z);
    atomicAdd(op + 3, w * vv.w);
}

__global__ void bias_add_kernel(float* __restrict__ out, const float* __restrict__ b, int n) {
    int i = blockIdx.x * blockDim.x + threadIdx.x;
    if (i >= n * 32) return;
    int f = (i & 31) * 4;
    float4 bv = *(const float4*)(b + f);
    float4 ov = *(float4*)(out + (size_t)i * 4);
    ov.x += bv.x; ov.y += bv.y; ov.z += bv.z; ov.w += bv.w;
    *(float4*)(out + (size_t)i * 4) = ov;
}

__global__ void finalize_max_b2_kernel(const unsigned* __restrict__ emax,
                                       const float* __restrict__ b2,
                                       float* __restrict__ out, int total) {
    int i = blockIdx.x * blockDim.x + threadIdx.x;
    if (i >= total) return;
    float v = fdecode(emax[i]);
    out[i] = isfinite(v) ? v + b2[i & (DIMF - 1)] : 0.f;
}

// ---------------- host orchestration ----------------
static inline int div_up(int a, int b) { return (a + b - 1) / b; }

struct Scratch {
    float *xl, *xp, *la, *pa, *q, *k, *v, *hs, *hd, *ss, *sd, *escore, *dsum, *P, *Q;
    float *Ahi, *Alo, *Bhi, *Blo;
    unsigned *mkey, *emax;
};

static void split(const float* x, float* hi, float* lo, int n) {
    int n4 = n / 4;
    split_kernel<<<div_up(n4, 256), 256>>>((const float4*)x, (float4*)hi, (float4*)lo, n4);
}

static void sgemm_ps(const Scratch& S, const float* bias, float* C, int M, int N, int K) {
    dim3 grid(N / 128, div_up(M, 128));
    mma3_ps_kernel<<<grid, 256, PS_SMEM_BYTES>>>(S.Ahi, S.Alo, S.Bhi, S.Blo, bias, C, M, N, K);
}

static void run_trans(const Scratch& S, const float* x, int n,
                      const int* src, const int* dst, int E,
                      const float* Wq, const float* bq, const float* Wk, const float* bk,
                      const float* Wv, const float* bv, const float* Ws, const float* bs,
                      float* out)
{
    split(x, S.Ahi, S.Alo, n * DIMF);
    split(Ws, S.Bhi, S.Blo, DIMF * DIMF); sgemm_ps(S, bs, out, n, DIMF, DIMF);
    split(Wq, S.Bhi, S.Blo, DIMF * DIMF); sgemm_ps(S, bq, S.q, n, DIMF, DIMF);
    split(Wk, S.Bhi, S.Blo, DIMF * DIMF); sgemm_ps(S, bk, S.k, n, DIMF, DIMF);
    split(Wv, S.Bhi, S.Blo, DIMF * DIMF); sgemm_ps(S, bv, S.v, n, DIMF, DIMF);
    reset_softmax_kernel<<<div_up(n, 256), 256>>>(S.mkey, S.dsum, n);
    float scale = 1.f / sqrtf((float)DIMF);
    trans_score_kernel<<<div_up(E * 32, 256), 256>>>(S.q, S.k, src, dst, S.escore, S.mkey, E, scale);
    expsum_kernel<<<div_up(E, 256), 256>>>(S.escore, S.mkey, S.dsum, dst, E);
    aggregate_kernel<<<div_up(E * 32, 256), 256>>>(S.escore, S.dsum, S.v, src, dst, out, E);
}

static void run_gat(const Scratch& S, const float* xs, int ns, const float* xd, int nd,
                    const int* src, const int* dst, int E,
                    const float* W, const float* a_src, const float* a_dst, const float* b,
                    float* out)
{
    split(W, S.Bhi, S.Blo, DIMF * DIMF);
    split(xs, S.Ahi, S.Alo, ns * DIMF); sgemm_ps(S, nullptr, S.hs, ns, DIMF, DIMF);
    split(xd, S.Ahi, S.Alo, nd * DIMF); sgemm_ps(S, nullptr, S.hd, nd, DIMF, DIMF);
    node_dot_kernel<<<div_up(ns * 32, 256), 256>>>(S.hs, a_src, S.ss, ns);
    node_dot_kernel<<<div_up(nd * 32, 256), 256>>>(S.hd, a_dst, S.sd, nd);
    reset_softmax_kernel<<<div_up(nd, 256), 256>>>(S.mkey, S.dsum, nd);
    gat_score_kernel<<<div_up(E, 256), 256>>>(S.ss, S.sd, src, dst, S.escore, S.mkey, E);
    expsum_kernel<<<div_up(E, 256), 256>>>(S.escore, S.mkey, S.dsum, dst, E);
    aggregate_kernel<<<div_up(E * 32, 256), 256>>>(S.escore, S.dsum, S.hs, src, dst, out, E);
    bias_add_kernel<<<div_up(nd * 32, 256), 256>>>(out, b, nd);
}

static void run_edge(const Scratch& S, const float* x, int n,
                     const int* src, const int* dst, int E,
                     const float* W1, const float* b1, const float* W2, const float* b2,
                     float* out)
{
    const float* W1a = W1;
    const float* W1b = W1 + 128 * 512;
    split(x, S.Ahi, S.Alo, n * DIMF);
    split(W1a, S.Bhi, S.Blo, 128 * 512); sgemm_ps(S, nullptr, S.P, n, 512, DIMF);
    split(W1b, S.Bhi, S.Blo, 128 * 512); sgemm_ps(S, nullptr, S.Q, n, 512, DIMF);
    fill_u32_kernel<<<div_up(n * DIMF, 256), 256>>>(S.emax, NEG_INF_KEY, n * DIMF);
    split(W2, S.Bhi, S.Blo, 512 * 128);
    dim3 grid(1, div_up(E, BM));
    edge_fused_ps_kernel<<<grid, 256, EDGE_SMEM_BYTES>>>(S.P, S.Q, b1, S.Bhi, S.Blo,
                                                         src, dst, S.emax, E);
    finalize_max_b2_kernel<<<div_up(n * DIMF, 256), 256>>>(S.emax, b2, out, n * DIMF);
}

extern "C" void kernel_launch(void* const* d_in, const int* in_sizes, int n_in,
                              void* d_out, int out_size)
{
    const float* x_lego  = (const float*)d_in[0];
    const float* x_point = (const float*)d_in[1];
    const float* tWq = (const float*)d_in[2];
    const float* tbq = (const float*)d_in[3];
    const float* tWk = (const float*)d_in[4];
    const float* tbk = (const float*)d_in[5];
    const float* tWv = (const float*)d_in[6];
    const float* tbv = (const float*)d_in[7];
    const float* tWs = (const float*)d_in[8];
    const float* tbs = (const float*)d_in[9];
    const float* eW1 = (const float*)d_in[10];
    const float* eb1 = (const float*)d_in[11];
    const float* eW2 = (const float*)d_in[12];
    const float* eb2 = (const float*)d_in[13];
    const float* gW  = (const float*)d_in[14];
    const float* gAs = (const float*)d_in[15];
    const float* gAd = (const float*)d_in[16];
    const float* gb  = (const float*)d_in[17];
    const int* ll_src = (const int*)d_in[18];
    const int* ll_dst = (const int*)d_in[19];
    const int* pp_src = (const int*)d_in[20];
    const int* pp_dst = (const int*)d_in[21];
    const int* lp_src = (const int*)d_in[22];
    const int* lp_dst = (const int*)d_in[23];
    const int* pl_src = (const int*)d_in[24];
    const int* pl_dst = (const int*)d_in[25];

    cudaFuncSetAttribute(mma3_ps_kernel, cudaFuncAttributeMaxDynamicSharedMemorySize,
                         PS_SMEM_BYTES);
    cudaFuncSetAttribute(edge_fused_ps_kernel, cudaFuncAttributeMaxDynamicSharedMemorySize,
                         EDGE_SMEM_BYTES);

    Scratch S;
    cudaGetSymbolAddress((void**)&S.xl, g_xl);
    cudaGetSymbolAddress((void**)&S.xp, g_xp);
    cudaGetSymbolAddress((void**)&S.la, g_la);
    cudaGetSymbolAddress((void**)&S.pa, g_pa);
    cudaGetSymbolAddress((void**)&S.q,  g_q);
    cudaGetSymbolAddress((void**)&S.k,  g_k);
    cudaGetSymbolAddress((void**)&S.v,  g_v);
    cudaGetSymbolAddress((void**)&S.hs, g_hs);
    cudaGetSymbolAddress((void**)&S.hd, g_hd);
    cudaGetSymbolAddress((void**)&S.ss, g_ss);
    cudaGetSymbolAddress((void**)&S.sd, g_sd);
    cudaGetSymbolAddress((void**)&S.escore, g_escore);
    cudaGetSymbolAddress((void**)&S.dsum, g_dsum);
    cudaGetSymbolAddress((void**)&S.P, g_P);
    cudaGetSymbolAddress((void**)&S.Q, g_Q);
    cudaGetSymbolAddress((void**)&S.mkey, g_mkey);
    cudaGetSymbolAddress((void**)&S.emax, g_emax);
    cudaGetSymbolAddress((void**)&S.Ahi, g_Ahi);
    cudaGetSymbolAddress((void**)&S.Alo, g_Alo);
    cudaGetSymbolAddress((void**)&S.Bhi, g_Bhi);
    cudaGetSymbolAddress((void**)&S.Blo, g_Blo);

    cudaMemcpyAsync(S.xl, x_lego,  (size_t)N_LEGO * DIMF * sizeof(float),  cudaMemcpyDeviceToDevice);
    cudaMemcpyAsync(S.xp, x_point, (size_t)N_POINT * DIMF * sizeof(float), cudaMemcpyDeviceToDevice);

    for (int layer = 0; layer < 2; layer++) {
        int iA = 2 * layer, iB = 2 * layer + 1;
        int i_lp = 2 * layer, i_pl = 2 * layer + 1;

        run_trans(S, S.xl, N_LEGO, ll_src, ll_dst, NE_LL,
                  tWq + iA * DIMF * DIMF, tbq + iA * DIMF,
                  tWk + iA * DIMF * DIMF, tbk + iA * DIMF,
                  tWv + iA * DIMF * DIMF, tbv + iA * DIMF,
                  tWs + iA * DIMF * DIMF, tbs + iA * DIMF,
                  S.la);
        run_gat(S, S.xp, N_POINT, S.xl, N_LEGO, pl_src, pl_dst, NE_PL,
                gW + i_pl * DIMF * DIMF, gAs + i_pl * DIMF, gAd + i_pl * DIMF, gb + i_pl * DIMF,
                S.la);

        run_edge(S, S.xp, N_POINT, pp_src, pp_dst, NE_PP,
                 eW1 + (size_t)iA * 256 * 512, eb1 + iA * 512,
                 eW2 + (size_t)iA * 512 * DIMF, eb2 + iA * DIMF,
                 S.pa);
        run_gat(S, S.xl, N_LEGO, S.xp, N_POINT, lp_src, lp_dst, NE_LP,
                gW + i_lp * DIMF * DIMF, gAs + i_lp * DIMF, gAd + i_lp * DIMF, gb + i_lp * DIMF,
                S.pa);

        run_trans(S, S.la, N_LEGO, ll_src, ll_dst, NE_LL,
                  tWq + iB * DIMF * DIMF, tbq + iB * DIMF,
                  tWk + iB * DIMF * DIMF, tbk + iB * DIMF,
                  tWv + iB * DIMF * DIMF, tbv + iB * DIMF,
                  tWs + iB * DIMF * DIMF, tbs + iB * DIMF,
                  S.xl);
        run_edge(S, S.pa, N_POINT, pp_src, pp_dst, NE_PP,
                 eW1 + (size_t)iB * 256 * 512, eb1 + iB * 512,
                 eW2 + (size_t)iB * 512 * DIMF, eb2 + iB * DIMF,
                 S.xp);
    }

    float* out = (float*)d_out;
    cudaMemcpyAsync(out, S.xl, (size_t)N_LEGO * DIMF * sizeof(float), cudaMemcpyDeviceToDevice);
    cudaMemcpyAsync(out + (size_t)N_LEGO * DIMF, S.xp, (size_t)N_POINT * DIMF * sizeof(float),
                    cudaMemcpyDeviceToDevice);
}